// round 2
// baseline (speedup 1.0000x reference)
#include <cuda_runtime.h>
#include <cuda_bf16.h>
#include <math.h>

#define Bc 4
#define Lc 1536
#define Kc 30
#define EF 128
#define EIN 167
#define NSLOT 48   // Lc / 32

// scratch (device globals; no allocation allowed)
__device__ float g_O[Bc*Lc*9];
__device__ int   g_Eidx[Bc*Lc*Kc];
__device__ float g_Dn[Bc*Lc*Kc];
__device__ float g_WT[EIN*EF];

// ---------------------------------------------------------------------------
// Kernel 0: transpose W_edge (128x167) -> WT (167x128) for coalesced GEMM reads
// ---------------------------------------------------------------------------
__global__ void k_transpose(const float* __restrict__ W)
{
    int idx = blockIdx.x * blockDim.x + threadIdx.x;
    if (idx < EIN * EF) {
        int k = idx / EF;
        int f = idx - k * EF;
        g_WT[k * EF + f] = W[f * EIN + k];
    }
}

// ---------------------------------------------------------------------------
// Kernel 1: per-node orientation frame O(i) = [o1; n2; o1 x n2] (rows), padded
// O(i) valid for 1 <= i <= L-3, zero otherwise (matches jnp.pad((1,2)))
// ---------------------------------------------------------------------------
__device__ __forceinline__ void norml3(float& x, float& y, float& z)
{
    float rn = rsqrtf(x*x + y*y + z*z + 1e-12f);
    x *= rn; y *= rn; z *= rn;
}

__global__ void k_frames(const float* __restrict__ Ca)
{
    int r = blockIdx.x * blockDim.x + threadIdx.x;
    if (r >= Bc * Lc) return;
    int b = r / Lc, i = r - b * Lc;
    float* O = &g_O[(size_t)r * 9];
    if (i < 1 || i > Lc - 3) {
        #pragma unroll
        for (int t = 0; t < 9; t++) O[t] = 0.f;
        return;
    }
    const float* cab = Ca + (size_t)b * Lc * 3;
    // need Ca[i-1], Ca[i], Ca[i+1]  -> U at t=i-1 (u2) and t=i (u1)
    float p0x = cab[(i-1)*3+0], p0y = cab[(i-1)*3+1], p0z = cab[(i-1)*3+2];
    float p1x = cab[(i  )*3+0], p1y = cab[(i  )*3+1], p1z = cab[(i  )*3+2];
    float p2x = cab[(i+1)*3+0], p2y = cab[(i+1)*3+1], p2z = cab[(i+1)*3+2];

    // U(t) = norml(dX * band(dn))
    float ax = p1x - p0x, ay = p1y - p0y, az = p1z - p0z;
    float an = sqrtf(ax*ax + ay*ay + az*az + 1e-12f);
    float ab = (an > 3.6f && an < 4.0f) ? 1.f : 0.f;
    float u2x = ax*ab, u2y = ay*ab, u2z = az*ab;
    norml3(u2x, u2y, u2z);

    float bx = p2x - p1x, by = p2y - p1y, bz = p2z - p1z;
    float bn = sqrtf(bx*bx + by*by + bz*bz + 1e-12f);
    float bb = (bn > 3.6f && bn < 4.0f) ? 1.f : 0.f;
    float u1x = bx*bb, u1y = by*bb, u1z = bz*bb;
    norml3(u1x, u1y, u1z);

    // n2 = norml(cross(u2, u1))
    float n2x = u2y*u1z - u2z*u1y;
    float n2y = u2z*u1x - u2x*u1z;
    float n2z = u2x*u1y - u2y*u1x;
    norml3(n2x, n2y, n2z);

    // o1 = norml(u2 - u1)
    float o1x = u2x - u1x, o1y = u2y - u1y, o1z = u2z - u1z;
    norml3(o1x, o1y, o1z);

    // third row = cross(o1, n2)
    float cx = o1y*n2z - o1z*n2y;
    float cy = o1z*n2x - o1x*n2z;
    float cz = o1x*n2y - o1y*n2x;

    O[0] = o1x; O[1] = o1y; O[2] = o1z;
    O[3] = n2x; O[4] = n2y; O[5] = n2z;
    O[6] = cx;  O[7] = cy;  O[8] = cz;
}

// ---------------------------------------------------------------------------
// Kernel 2: top-K (K=30) smallest adjusted distances per (b,i).
// One warp per row; 48 distances per lane in registers; stable selection via
// u64 key = (float_bits(d) << 32) | j  (d >= 0, so bit order == value order;
// lower index wins ties, matching jax.lax.top_k).
// ---------------------------------------------------------------------------
__global__ void k_topk(const float* __restrict__ Ca, const float* __restrict__ mask,
                       float* __restrict__ out, long long out_elems)
{
    int warp = threadIdx.x >> 5;
    int lane = threadIdx.x & 31;
    int r = blockIdx.x * (blockDim.x >> 5) + warp;
    if (r >= Bc * Lc) return;
    int b = r / Lc, i = r - b * Lc;
    const float* cab = Ca + (size_t)b * Lc * 3;
    const float* mb  = mask + (size_t)b * Lc;

    float cix = cab[i*3+0], ciy = cab[i*3+1], ciz = cab[i*3+2];
    float mi  = mb[i];

    float d[NSLOT];
    unsigned long long valid = 0ull;
    float dmax = 0.f;
    #pragma unroll
    for (int s = 0; s < NSLOT; s++) {
        int j = s * 32 + lane;
        float dx = cab[j*3+0] - cix;
        float dy = cab[j*3+1] - ciy;
        float dz = cab[j*3+2] - ciz;
        float dist = sqrtf(dx*dx + dy*dy + dz*dz + 1e-6f);
        float m2 = mi * mb[j];
        float D = m2 * dist;
        d[s] = D;
        if (m2 != 0.f) valid |= (1ull << s);
        dmax = fmaxf(dmax, D);
    }
    #pragma unroll
    for (int o = 16; o; o >>= 1)
        dmax = fmaxf(dmax, __shfl_xor_sync(0xffffffffu, dmax, o));
    // Dadj: masked entries become 0 + 1*Dmax
    #pragma unroll
    for (int s = 0; s < NSLOT; s++)
        if (!((valid >> s) & 1ull)) d[s] = dmax;

    unsigned long long removed = 0ull;
    for (int t = 0; t < Kc; t++) {
        unsigned long long best = ~0ull;
        #pragma unroll
        for (int s = 0; s < NSLOT; s++) {
            if (!((removed >> s) & 1ull)) {
                unsigned long long key =
                    ((unsigned long long)__float_as_uint(d[s]) << 32) |
                    (unsigned)(s * 32 + lane);
                if (key < best) best = key;
            }
        }
        #pragma unroll
        for (int o = 16; o; o >>= 1) {
            unsigned long long oth = __shfl_xor_sync(0xffffffffu, best, o);
            if (oth < best) best = oth;
        }
        int j = (int)(best & 0xffffffffull);
        float val = __uint_as_float((unsigned)(best >> 32));
        if (lane == 0) {
            g_Eidx[(size_t)r * Kc + t] = j;
            g_Dn  [(size_t)r * Kc + t] = val;
            long long off = (long long)Bc * Lc * Kc * EF + (long long)r * Kc + t;
            if (off < out_elems) out[off] = (float)j;   // E_idx as float
        }
        if ((j & 31) == lane) removed |= (1ull << (j >> 5));
    }
}

// ---------------------------------------------------------------------------
// Kernel 3: fused per-(b,i): edge features (167) -> GEMM (x128) -> LayerNorm
// ---------------------------------------------------------------------------
__device__ __forceinline__ float edist(const float* a, const float* bp)
{
    float dx = a[0]-bp[0], dy = a[1]-bp[1], dz = a[2]-bp[2];
    return sqrtf(dx*dx + dy*dy + dz*dz + 1e-6f);
}
__device__ __forceinline__ float fsign(float x)
{
    return (float)((x > 0.f) - (x < 0.f));
}

__global__ void k_edge(const float* __restrict__ Ca,
                       const int* __restrict__ ridx, const int* __restrict__ chain,
                       const float* __restrict__ W_pos, const float* __restrict__ b_pos,
                       const float* __restrict__ gamma, const float* __restrict__ beta,
                       float* __restrict__ out, long long out_elems)
{
    __shared__ float s_feat[Kc][168];   // 167 used, padded
    __shared__ float s_out[Kc][EF];
    __shared__ float s_dist[Kc][9];
    __shared__ float s_misc[18];        // O_i(9), ci(3), cim(3), cip(3)
    __shared__ int   s_ri, s_ch;

    int r = blockIdx.x;
    int b = r / Lc, i = r - b * Lc;
    int tid = threadIdx.x;
    const float* cab = Ca + (size_t)b * Lc * 3;

    if (tid == 0) {
        #pragma unroll
        for (int t = 0; t < 9; t++) s_misc[t] = g_O[(size_t)r * 9 + t];
        s_misc[ 9] = cab[i*3+0]; s_misc[10] = cab[i*3+1]; s_misc[11] = cab[i*3+2];
        if (i > 0)      { s_misc[12] = cab[(i-1)*3+0]; s_misc[13] = cab[(i-1)*3+1]; s_misc[14] = cab[(i-1)*3+2]; }
        else            { s_misc[12] = 0.f; s_misc[13] = 0.f; s_misc[14] = 0.f; }
        if (i < Lc - 1) { s_misc[15] = cab[(i+1)*3+0]; s_misc[16] = cab[(i+1)*3+1]; s_misc[17] = cab[(i+1)*3+2]; }
        else            { s_misc[15] = 0.f; s_misc[16] = 0.f; s_misc[17] = 0.f; }
        s_ri = ridx[r]; s_ch = chain[r];
    }
    __syncthreads();

    if (tid < Kc) {
        int j = g_Eidx[(size_t)r * Kc + tid];
        const float* Oi  = &s_misc[0];
        const float* ci  = &s_misc[9];
        const float* cim = &s_misc[12];
        const float* cip = &s_misc[15];

        float cj[3], cjm[3], cjp[3];
        cj[0] = cab[j*3+0]; cj[1] = cab[j*3+1]; cj[2] = cab[j*3+2];
        if (j > 0)      { cjm[0] = cab[(j-1)*3+0]; cjm[1] = cab[(j-1)*3+1]; cjm[2] = cab[(j-1)*3+2]; }
        else            { cjm[0] = cjm[1] = cjm[2] = 0.f; }
        if (j < Lc - 1) { cjp[0] = cab[(j+1)*3+0]; cjp[1] = cab[(j+1)*3+1]; cjp[2] = cab[(j+1)*3+2]; }
        else            { cjp[0] = cjp[1] = cjp[2] = 0.f; }

        s_dist[tid][0] = g_Dn[(size_t)r * Kc + tid];      // D_neighbors (topk values)
        s_dist[tid][1] = edist(cim, cjm);  // Ca0,Ca0
        s_dist[tid][2] = edist(cip, cjp);  // Ca2,Ca2
        s_dist[tid][3] = edist(cim, cj );  // Ca0,Ca
        s_dist[tid][4] = edist(cim, cjp);  // Ca0,Ca2
        s_dist[tid][5] = edist(ci , cjm);  // Ca,Ca0
        s_dist[tid][6] = edist(ci , cjp);  // Ca,Ca2
        s_dist[tid][7] = edist(cip, cjm);  // Ca2,Ca0
        s_dist[tid][8] = edist(cip, cj );  // Ca2,Ca

        // positional embedding
        int off = s_ri - ridx[(size_t)b * Lc + j];
        int ech = (s_ch == chain[(size_t)b * Lc + j]);
        int dpos = ech ? min(max(off + 32, 0), 64) : 65;
        #pragma unroll
        for (int f = 0; f < 16; f++)
            s_feat[tid][f] = W_pos[f * 66 + dpos] + b_pos[f];

        // dU = norml(O_i @ (Ca_j - Ca_i))
        float vx = cj[0]-ci[0], vy = cj[1]-ci[1], vz = cj[2]-ci[2];
        float w0 = Oi[0]*vx + Oi[1]*vy + Oi[2]*vz;
        float w1 = Oi[3]*vx + Oi[4]*vy + Oi[5]*vz;
        float w2 = Oi[6]*vx + Oi[7]*vy + Oi[8]*vz;
        float rn = rsqrtf(w0*w0 + w1*w1 + w2*w2 + 1e-12f);
        s_feat[tid][160] = w0*rn; s_feat[tid][161] = w1*rn; s_feat[tid][162] = w2*rn;

        // R = O_i^T @ O_j ; quaternion
        float Oj[9];
        #pragma unroll
        for (int t = 0; t < 9; t++) Oj[t] = g_O[((size_t)b * Lc + j) * 9 + t];
        float R[3][3];
        #pragma unroll
        for (int a = 0; a < 3; a++)
            #pragma unroll
            for (int m = 0; m < 3; m++)
                R[a][m] = Oi[0*3+a]*Oj[0*3+m] + Oi[1*3+a]*Oj[1*3+m] + Oi[2*3+a]*Oj[2*3+m];
        float Rxx = R[0][0], Ryy = R[1][1], Rzz = R[2][2];
        float mx = 0.5f * sqrtf(fabsf(1.f + Rxx - Ryy - Rzz) + 1e-12f);
        float my = 0.5f * sqrtf(fabsf(1.f - Rxx + Ryy - Rzz) + 1e-12f);
        float mz = 0.5f * sqrtf(fabsf(1.f - Rxx - Ryy + Rzz) + 1e-12f);
        float qx = fsign(R[2][1] - R[1][2]) * mx;
        float qy = fsign(R[0][2] - R[2][0]) * my;
        float qz = fsign(R[1][0] - R[0][1]) * mz;
        float qw = 0.5f * sqrtf(fmaxf(1.f + Rxx + Ryy + Rzz, 0.f) + 1e-12f);
        float qn = rsqrtf(qx*qx + qy*qy + qz*qz + qw*qw + 1e-12f);
        s_feat[tid][163] = qx*qn; s_feat[tid][164] = qy*qn;
        s_feat[tid][165] = qz*qn; s_feat[tid][166] = qw*qn;
    }
    __syncthreads();

    // RBFs: 30 edges x 9 dists x 16 mus
    for (int idx = tid; idx < Kc * 144; idx += 256) {
        int e = idx / 144;
        int rem = idx - e * 144;
        int rr = rem >> 4;
        int m = rem & 15;
        float D = s_dist[e][rr];
        float mu = 2.0f + (4.0f / 3.0f) * (float)m;   // linspace(2,22,16)
        float t = (D - mu) * 0.8f;                    // / 1.25
        s_feat[e][16 + rem] = expf(-t * t);
    }
    __syncthreads();

    // GEMM: out[e][f] = sum_k feat[e][k] * W_edge[f][k] = sum_k feat[e][k]*WT[k][f]
    {
        int h = tid >> 7;       // 0 or 1 -> edge halves
        int f = tid & 127;
        float acc[15];
        #pragma unroll
        for (int t = 0; t < 15; t++) acc[t] = 0.f;
        for (int k = 0; k < EIN; k++) {
            float w = g_WT[k * EF + f];
            #pragma unroll
            for (int t = 0; t < 15; t++)
                acc[t] += w * s_feat[h * 15 + t][k];
        }
        #pragma unroll
        for (int t = 0; t < 15; t++) s_out[h * 15 + t][f] = acc[t];
    }
    __syncthreads();

    // LayerNorm per edge over 128 features; warp per edge (round-robin)
    {
        int warp = tid >> 5, lane = tid & 31;
        for (int e = warp; e < Kc; e += 8) {
            float v[4];
            #pragma unroll
            for (int q = 0; q < 4; q++) v[q] = s_out[e][lane + 32 * q];
            float sum = v[0] + v[1] + v[2] + v[3];
            #pragma unroll
            for (int o = 16; o; o >>= 1) sum += __shfl_xor_sync(0xffffffffu, sum, o);
            float mu = sum * (1.f / 128.f);
            float ss = 0.f;
            #pragma unroll
            for (int q = 0; q < 4; q++) { float dv = v[q] - mu; ss += dv * dv; }
            #pragma unroll
            for (int o = 16; o; o >>= 1) ss += __shfl_xor_sync(0xffffffffu, ss, o);
            float var = ss * (1.f / 128.f);
            float rstd = rsqrtf(var + 1e-5f);
            long long base = ((long long)r * Kc + e) * EF;
            #pragma unroll
            for (int q = 0; q < 4; q++) {
                int fq = lane + 32 * q;
                long long o2 = base + fq;
                if (o2 < out_elems)
                    out[o2] = (v[q] - mu) * rstd * gamma[fq] + beta[fq];
            }
        }
    }
}

// ---------------------------------------------------------------------------
extern "C" void kernel_launch(void* const* d_in, const int* in_sizes, int n_in,
                              void* d_out, int out_size)
{
    const float* Ca     = (const float*)d_in[0];
    const float* mask   = (const float*)d_in[1];
    const int*   ridx   = (const int*)  d_in[2];
    const int*   chain  = (const int*)  d_in[3];
    const float* W_pos  = (const float*)d_in[4];
    const float* b_pos  = (const float*)d_in[5];
    const float* W_edge = (const float*)d_in[6];
    const float* gamma  = (const float*)d_in[7];
    const float* beta   = (const float*)d_in[8];
    float* out = (float*)d_out;
    long long out_elems = (long long)out_size;

    k_transpose<<<(EIN * EF + 255) / 256, 256>>>(W_edge);
    k_frames<<<(Bc * Lc + 255) / 256, 256>>>(Ca);
    k_topk<<<(Bc * Lc) / 8, 256>>>(Ca, mask, out, out_elems);
    k_edge<<<Bc * Lc, 256>>>(Ca, ridx, chain, W_pos, b_pos, gamma, beta, out, out_elems);
}

// round 3
// speedup vs baseline: 1.4485x; 1.4485x over previous
#include <cuda_runtime.h>
#include <cuda_bf16.h>
#include <math.h>

#define Bc 4
#define Lc 1536
#define Kc 30
#define EF 128
#define EIN 167
#define NSLOT 48   // Lc / 32

// GEMM k-dim after removing 16 pos dims: 151, padded to 152 = 38 float4 groups
#define KD 151
#define KG 38

// scratch (device globals; no allocation allowed)
__device__ float  g_O[Bc*Lc*9];
__device__ int    g_Eidx[Bc*Lc*Kc];
__device__ float  g_Dn[Bc*Lc*Kc];
__device__ float4 g_WT2[KG*EF];     // WT2[kg][f] = W_edge[f][16+4kg .. 16+4kg+3] (0-padded)
__device__ float  g_T[66*EF];       // T[d][f] = sum_p (W_pos[p][d]+b_pos[p]) * W_edge[f][p]

// ---------------------------------------------------------------------------
// Kernel 0: build WT2 (packed transposed weights) and g_T (pos-embed projection)
// ---------------------------------------------------------------------------
__global__ void k_prep(const float* __restrict__ W,
                       const float* __restrict__ W_pos, const float* __restrict__ b_pos)
{
    int idx = blockIdx.x * blockDim.x + threadIdx.x;
    const int NW = KG * EF * 4;      // 19456
    if (idx < NW) {
        int q = idx & 3;
        int f = (idx >> 2) & (EF - 1);
        int g = idx >> 9;
        int kk = 4 * g + q;          // index into the 151 non-pos dims
        float v = 0.f;
        if (kk < KD) v = W[f * EIN + 16 + kk];
        ((float*)g_WT2)[idx] = v;
    } else {
        int j = idx - NW;            // 66*128 entries
        if (j < 66 * EF) {
            int d = j >> 7;
            int f = j & (EF - 1);
            float acc = 0.f;
            #pragma unroll
            for (int p = 0; p < 16; p++)
                acc += (W_pos[p * 66 + d] + b_pos[p]) * W[f * EIN + p];
            g_T[d * EF + f] = acc;
        }
    }
}

// ---------------------------------------------------------------------------
// Kernel 1: per-node orientation frame O(i) = [o1; n2; o1 x n2] (rows), padded
// ---------------------------------------------------------------------------
__device__ __forceinline__ void norml3(float& x, float& y, float& z)
{
    float rn = rsqrtf(x*x + y*y + z*z + 1e-12f);
    x *= rn; y *= rn; z *= rn;
}

__global__ void k_frames(const float* __restrict__ Ca)
{
    int r = blockIdx.x * blockDim.x + threadIdx.x;
    if (r >= Bc * Lc) return;
    int b = r / Lc, i = r - b * Lc;
    float* O = &g_O[(size_t)r * 9];
    if (i < 1 || i > Lc - 3) {
        #pragma unroll
        for (int t = 0; t < 9; t++) O[t] = 0.f;
        return;
    }
    const float* cab = Ca + (size_t)b * Lc * 3;
    float p0x = cab[(i-1)*3+0], p0y = cab[(i-1)*3+1], p0z = cab[(i-1)*3+2];
    float p1x = cab[(i  )*3+0], p1y = cab[(i  )*3+1], p1z = cab[(i  )*3+2];
    float p2x = cab[(i+1)*3+0], p2y = cab[(i+1)*3+1], p2z = cab[(i+1)*3+2];

    float ax = p1x - p0x, ay = p1y - p0y, az = p1z - p0z;
    float an = sqrtf(ax*ax + ay*ay + az*az + 1e-12f);
    float ab = (an > 3.6f && an < 4.0f) ? 1.f : 0.f;
    float u2x = ax*ab, u2y = ay*ab, u2z = az*ab;
    norml3(u2x, u2y, u2z);

    float bx = p2x - p1x, by = p2y - p1y, bz = p2z - p1z;
    float bn = sqrtf(bx*bx + by*by + bz*bz + 1e-12f);
    float bb = (bn > 3.6f && bn < 4.0f) ? 1.f : 0.f;
    float u1x = bx*bb, u1y = by*bb, u1z = bz*bb;
    norml3(u1x, u1y, u1z);

    float n2x = u2y*u1z - u2z*u1y;
    float n2y = u2z*u1x - u2x*u1z;
    float n2z = u2x*u1y - u2y*u1x;
    norml3(n2x, n2y, n2z);

    float o1x = u2x - u1x, o1y = u2y - u1y, o1z = u2z - u1z;
    norml3(o1x, o1y, o1z);

    float cx = o1y*n2z - o1z*n2y;
    float cy = o1z*n2x - o1x*n2z;
    float cz = o1x*n2y - o1y*n2x;

    O[0] = o1x; O[1] = o1y; O[2] = o1z;
    O[3] = n2x; O[4] = n2y; O[5] = n2z;
    O[6] = cx;  O[7] = cy;  O[8] = cz;
}

// ---------------------------------------------------------------------------
// Kernel 2: top-K (K=30) smallest adjusted distances per (b,i).
// ---------------------------------------------------------------------------
__global__ void k_topk(const float* __restrict__ Ca, const float* __restrict__ mask,
                       float* __restrict__ out, long long out_elems)
{
    int warp = threadIdx.x >> 5;
    int lane = threadIdx.x & 31;
    int r = blockIdx.x * (blockDim.x >> 5) + warp;
    if (r >= Bc * Lc) return;
    int b = r / Lc, i = r - b * Lc;
    const float* cab = Ca + (size_t)b * Lc * 3;
    const float* mb  = mask + (size_t)b * Lc;

    float cix = cab[i*3+0], ciy = cab[i*3+1], ciz = cab[i*3+2];
    float mi  = mb[i];

    float d[NSLOT];
    unsigned long long valid = 0ull;
    float dmax = 0.f;
    #pragma unroll
    for (int s = 0; s < NSLOT; s++) {
        int j = s * 32 + lane;
        float dx = cab[j*3+0] - cix;
        float dy = cab[j*3+1] - ciy;
        float dz = cab[j*3+2] - ciz;
        float dist = sqrtf(dx*dx + dy*dy + dz*dz + 1e-6f);
        float m2 = mi * mb[j];
        float D = m2 * dist;
        d[s] = D;
        if (m2 != 0.f) valid |= (1ull << s);
        dmax = fmaxf(dmax, D);
    }
    #pragma unroll
    for (int o = 16; o; o >>= 1)
        dmax = fmaxf(dmax, __shfl_xor_sync(0xffffffffu, dmax, o));
    #pragma unroll
    for (int s = 0; s < NSLOT; s++)
        if (!((valid >> s) & 1ull)) d[s] = dmax;

    unsigned long long removed = 0ull;
    for (int t = 0; t < Kc; t++) {
        unsigned long long best = ~0ull;
        #pragma unroll
        for (int s = 0; s < NSLOT; s++) {
            if (!((removed >> s) & 1ull)) {
                unsigned long long key =
                    ((unsigned long long)__float_as_uint(d[s]) << 32) |
                    (unsigned)(s * 32 + lane);
                if (key < best) best = key;
            }
        }
        #pragma unroll
        for (int o = 16; o; o >>= 1) {
            unsigned long long oth = __shfl_xor_sync(0xffffffffu, best, o);
            if (oth < best) best = oth;
        }
        int j = (int)(best & 0xffffffffull);
        float val = __uint_as_float((unsigned)(best >> 32));
        if (lane == 0) {
            g_Eidx[(size_t)r * Kc + t] = j;
            g_Dn  [(size_t)r * Kc + t] = val;
            long long off = (long long)Bc * Lc * Kc * EF + (long long)r * Kc + t;
            if (off < out_elems) out[off] = (float)j;   // E_idx as float
        }
        if ((j & 31) == lane) removed |= (1ull << (j >> 5));
    }
}

// ---------------------------------------------------------------------------
// Kernel 3: fused per-(b,i): edge features (151) -> GEMM (x128) -> LayerNorm
// ---------------------------------------------------------------------------
__device__ __forceinline__ float edist(const float* a, const float* bp)
{
    float dx = a[0]-bp[0], dy = a[1]-bp[1], dz = a[2]-bp[2];
    return sqrtf(dx*dx + dy*dy + dz*dz + 1e-6f);
}
__device__ __forceinline__ float fsign(float x)
{
    return (float)((x > 0.f) - (x < 0.f));
}

__global__ void __launch_bounds__(256)
k_edge(const float* __restrict__ Ca,
       const int* __restrict__ ridx, const int* __restrict__ chain,
       const float* __restrict__ gamma, const float* __restrict__ beta,
       float* __restrict__ out, long long out_elems)
{
    // s_feat: 32 edge rows (30 real + 2 dummy), 152 k-dims (float4-aligned)
    __shared__ __align__(16) float s_feat[32][KG*4];
    __shared__ float s_out[Kc][EF];
    __shared__ float s_dist[Kc][9];
    __shared__ float s_misc[18];        // O_i(9), ci(3), cim(3), cip(3)
    __shared__ int   s_dpos[32];
    __shared__ int   s_ri, s_ch;

    int r = blockIdx.x;
    int b = r / Lc, i = r - b * Lc;
    int tid = threadIdx.x;
    const float* cab = Ca + (size_t)b * Lc * 3;

    // zero feature buffer (covers k-padding and dummy edge rows)
    {
        float4 z4 = make_float4(0.f, 0.f, 0.f, 0.f);
        float4* sf4 = (float4*)s_feat;
        for (int idx = tid; idx < 32 * KG; idx += 256) sf4[idx] = z4;
        if (tid < 32) s_dpos[tid] = 0;
    }
    if (tid == 0) {
        #pragma unroll
        for (int t = 0; t < 9; t++) s_misc[t] = g_O[(size_t)r * 9 + t];
        s_misc[ 9] = cab[i*3+0]; s_misc[10] = cab[i*3+1]; s_misc[11] = cab[i*3+2];
        if (i > 0)      { s_misc[12] = cab[(i-1)*3+0]; s_misc[13] = cab[(i-1)*3+1]; s_misc[14] = cab[(i-1)*3+2]; }
        else            { s_misc[12] = 0.f; s_misc[13] = 0.f; s_misc[14] = 0.f; }
        if (i < Lc - 1) { s_misc[15] = cab[(i+1)*3+0]; s_misc[16] = cab[(i+1)*3+1]; s_misc[17] = cab[(i+1)*3+2]; }
        else            { s_misc[15] = 0.f; s_misc[16] = 0.f; s_misc[17] = 0.f; }
        s_ri = ridx[r]; s_ch = chain[r];
    }
    __syncthreads();

    if (tid < Kc) {
        int j = g_Eidx[(size_t)r * Kc + tid];
        const float* Oi  = &s_misc[0];
        const float* ci  = &s_misc[9];
        const float* cim = &s_misc[12];
        const float* cip = &s_misc[15];

        float cj[3], cjm[3], cjp[3];
        cj[0] = cab[j*3+0]; cj[1] = cab[j*3+1]; cj[2] = cab[j*3+2];
        if (j > 0)      { cjm[0] = cab[(j-1)*3+0]; cjm[1] = cab[(j-1)*3+1]; cjm[2] = cab[(j-1)*3+2]; }
        else            { cjm[0] = cjm[1] = cjm[2] = 0.f; }
        if (j < Lc - 1) { cjp[0] = cab[(j+1)*3+0]; cjp[1] = cab[(j+1)*3+1]; cjp[2] = cab[(j+1)*3+2]; }
        else            { cjp[0] = cjp[1] = cjp[2] = 0.f; }

        s_dist[tid][0] = g_Dn[(size_t)r * Kc + tid];
        s_dist[tid][1] = edist(cim, cjm);
        s_dist[tid][2] = edist(cip, cjp);
        s_dist[tid][3] = edist(cim, cj );
        s_dist[tid][4] = edist(cim, cjp);
        s_dist[tid][5] = edist(ci , cjm);
        s_dist[tid][6] = edist(ci , cjp);
        s_dist[tid][7] = edist(cip, cjm);
        s_dist[tid][8] = edist(cip, cj );

        // positional embedding index (projection through W_edge is precomputed in g_T)
        int off = s_ri - ridx[(size_t)b * Lc + j];
        int ech = (s_ch == chain[(size_t)b * Lc + j]);
        s_dpos[tid] = ech ? min(max(off + 32, 0), 64) : 65;

        // dU = norml(O_i @ (Ca_j - Ca_i))  -> dims 144..146
        float vx = cj[0]-ci[0], vy = cj[1]-ci[1], vz = cj[2]-ci[2];
        float w0 = Oi[0]*vx + Oi[1]*vy + Oi[2]*vz;
        float w1 = Oi[3]*vx + Oi[4]*vy + Oi[5]*vz;
        float w2 = Oi[6]*vx + Oi[7]*vy + Oi[8]*vz;
        float rn = rsqrtf(w0*w0 + w1*w1 + w2*w2 + 1e-12f);
        s_feat[tid][144] = w0*rn; s_feat[tid][145] = w1*rn; s_feat[tid][146] = w2*rn;

        // R = O_i^T @ O_j ; quaternion -> dims 147..150
        float Oj[9];
        #pragma unroll
        for (int t = 0; t < 9; t++) Oj[t] = g_O[((size_t)b * Lc + j) * 9 + t];
        float R[3][3];
        #pragma unroll
        for (int a = 0; a < 3; a++)
            #pragma unroll
            for (int m = 0; m < 3; m++)
                R[a][m] = Oi[0*3+a]*Oj[0*3+m] + Oi[1*3+a]*Oj[1*3+m] + Oi[2*3+a]*Oj[2*3+m];
        float Rxx = R[0][0], Ryy = R[1][1], Rzz = R[2][2];
        float mx = 0.5f * sqrtf(fabsf(1.f + Rxx - Ryy - Rzz) + 1e-12f);
        float my = 0.5f * sqrtf(fabsf(1.f - Rxx + Ryy - Rzz) + 1e-12f);
        float mz = 0.5f * sqrtf(fabsf(1.f - Rxx - Ryy + Rzz) + 1e-12f);
        float qx = fsign(R[2][1] - R[1][2]) * mx;
        float qy = fsign(R[0][2] - R[2][0]) * my;
        float qz = fsign(R[1][0] - R[0][1]) * mz;
        float qw = 0.5f * sqrtf(fmaxf(1.f + Rxx + Ryy + Rzz, 0.f) + 1e-12f);
        float qn = rsqrtf(qx*qx + qy*qy + qz*qz + qw*qw + 1e-12f);
        s_feat[tid][147] = qx*qn; s_feat[tid][148] = qy*qn;
        s_feat[tid][149] = qz*qn; s_feat[tid][150] = qw*qn;
    }
    __syncthreads();

    // RBFs: 30 edges x 9 dists x 16 mus -> dims 0..143
    for (int idx = tid; idx < Kc * 144; idx += 256) {
        int e = idx / 144;
        int rem = idx - e * 144;
        int rr = rem >> 4;
        int m = rem & 15;
        float D = s_dist[e][rr];
        float mu = 2.0f + (4.0f / 3.0f) * (float)m;
        float t = (D - mu) * 0.8f;
        s_feat[e][rem] = __expf(-t * t);
    }
    __syncthreads();

    // GEMM: 4 edge-groups (8 edges) x 64 f-pair threads; float4 over k.
    // Accumulators seeded from the precomputed positional projection g_T.
    {
        int g  = tid >> 6;          // edge group 0..3
        int fp = tid & 63;          // feature pair: f = 2*fp, 2*fp+1
        const float2* T2 = (const float2*)g_T;
        float acc0[8], acc1[8];
        #pragma unroll
        for (int e8 = 0; e8 < 8; e8++) {
            float2 t2 = T2[s_dpos[g * 8 + e8] * 64 + fp];
            acc0[e8] = t2.x;
            acc1[e8] = t2.y;
        }
        const float4* sf[8];
        #pragma unroll
        for (int e8 = 0; e8 < 8; e8++) sf[e8] = (const float4*)s_feat[g * 8 + e8];

        for (int kg = 0; kg < KG; kg++) {
            float4 wa = g_WT2[kg * EF + 2 * fp];
            float4 wb = g_WT2[kg * EF + 2 * fp + 1];
            #pragma unroll
            for (int e8 = 0; e8 < 8; e8++) {
                float4 fv = sf[e8][kg];
                acc0[e8] += fv.x * wa.x + fv.y * wa.y + fv.z * wa.z + fv.w * wa.w;
                acc1[e8] += fv.x * wb.x + fv.y * wb.y + fv.z * wb.z + fv.w * wb.w;
            }
        }
        #pragma unroll
        for (int e8 = 0; e8 < 8; e8++) {
            int e = g * 8 + e8;
            if (e < Kc) {
                s_out[e][2 * fp    ] = acc0[e8];
                s_out[e][2 * fp + 1] = acc1[e8];
            }
        }
    }
    __syncthreads();

    // LayerNorm per edge over 128 features; warp per edge (round-robin)
    {
        int warp = tid >> 5, lane = tid & 31;
        for (int e = warp; e < Kc; e += 8) {
            float v[4];
            #pragma unroll
            for (int q = 0; q < 4; q++) v[q] = s_out[e][lane + 32 * q];
            float sum = v[0] + v[1] + v[2] + v[3];
            #pragma unroll
            for (int o = 16; o; o >>= 1) sum += __shfl_xor_sync(0xffffffffu, sum, o);
            float mu = sum * (1.f / 128.f);
            float ss = 0.f;
            #pragma unroll
            for (int q = 0; q < 4; q++) { float dv = v[q] - mu; ss += dv * dv; }
            #pragma unroll
            for (int o = 16; o; o >>= 1) ss += __shfl_xor_sync(0xffffffffu, ss, o);
            float var = ss * (1.f / 128.f);
            float rstd = rsqrtf(var + 1e-5f);
            long long base = ((long long)r * Kc + e) * EF;
            #pragma unroll
            for (int q = 0; q < 4; q++) {
                int fq = lane + 32 * q;
                long long o2 = base + fq;
                if (o2 < out_elems)
                    out[o2] = (v[q] - mu) * rstd * gamma[fq] + beta[fq];
            }
        }
    }
}

// ---------------------------------------------------------------------------
extern "C" void kernel_launch(void* const* d_in, const int* in_sizes, int n_in,
                              void* d_out, int out_size)
{
    const float* Ca     = (const float*)d_in[0];
    const float* mask   = (const float*)d_in[1];
    const int*   ridx   = (const int*)  d_in[2];
    const int*   chain  = (const int*)  d_in[3];
    const float* W_pos  = (const float*)d_in[4];
    const float* b_pos  = (const float*)d_in[5];
    const float* W_edge = (const float*)d_in[6];
    const float* gamma  = (const float*)d_in[7];
    const float* beta   = (const float*)d_in[8];
    float* out = (float*)d_out;
    long long out_elems = (long long)out_size;

    const int prep_total = KG * EF * 4 + 66 * EF;
    k_prep<<<(prep_total + 255) / 256, 256>>>(W_edge, W_pos, b_pos);
    k_frames<<<(Bc * Lc + 255) / 256, 256>>>(Ca);
    k_topk<<<(Bc * Lc) / 8, 256>>>(Ca, mask, out, out_elems);
    k_edge<<<Bc * Lc, 256>>>(Ca, ridx, chain, gamma, beta, out, out_elems);
}

// round 4
// speedup vs baseline: 1.5546x; 1.0732x over previous
#include <cuda_runtime.h>
#include <cuda_bf16.h>
#include <math.h>

#define Bc 4
#define Lc 1536
#define Kc 30
#define EF 128
#define EIN 167
#define NSLOT 48   // Lc / 32

// GEMM k-dim after removing 16 pos dims: 151, padded to 152 = 76 k-pairs
#define KD 151
#define KPAD 152
#define KG 38      // 4-k groups

typedef unsigned long long ull;

// packed f32x2 FMA: acc.{lo,hi} += a.{lo,hi} * b.{lo,hi}
#define FMA_F32X2(acc, a, b) \
    asm("fma.rn.f32x2 %0, %1, %2, %0;" : "+l"(acc) : "l"(a), "l"(b))

// scratch (device globals; no allocation allowed)
__device__ float g_O[Bc*Lc*9];
__device__ int   g_Eidx[Bc*Lc*Kc];
__device__ float g_Dn[Bc*Lc*Kc];
__device__ __align__(16) ull g_WK[(KPAD/2)*EF];  // g_WK[kp][f] = {W[f][16+2kp], W[f][16+2kp+1]}
__device__ float g_T[66*EF];        // T[d][f] = sum_p (W_pos[p][d]+b_pos[p]) * W_edge[f][p]

// ---------------------------------------------------------------------------
// Kernel 0: build g_WK (k-pair packed weights) and g_T (pos-embed projection)
// ---------------------------------------------------------------------------
__global__ void k_prep(const float* __restrict__ W,
                       const float* __restrict__ W_pos, const float* __restrict__ b_pos)
{
    int idx = blockIdx.x * blockDim.x + threadIdx.x;
    const int NW = (KPAD/2) * EF;    // 9728
    if (idx < NW) {
        int kp = idx >> 7;
        int f  = idx & (EF - 1);
        int k0 = 2 * kp, k1 = 2 * kp + 1;
        float w0 = (k0 < KD) ? W[f * EIN + 16 + k0] : 0.f;
        float w1 = (k1 < KD) ? W[f * EIN + 16 + k1] : 0.f;
        g_WK[idx] = ((ull)__float_as_uint(w1) << 32) | (ull)__float_as_uint(w0);
    } else {
        int j = idx - NW;            // 66*128 entries
        if (j < 66 * EF) {
            int d = j >> 7;
            int f = j & (EF - 1);
            float acc = 0.f;
            #pragma unroll
            for (int p = 0; p < 16; p++)
                acc += (W_pos[p * 66 + d] + b_pos[p]) * W[f * EIN + p];
            g_T[d * EF + f] = acc;
        }
    }
}

// ---------------------------------------------------------------------------
// Kernel 1: per-node orientation frame O(i) = [o1; n2; o1 x n2] (rows), padded
// ---------------------------------------------------------------------------
__device__ __forceinline__ void norml3(float& x, float& y, float& z)
{
    float rn = rsqrtf(x*x + y*y + z*z + 1e-12f);
    x *= rn; y *= rn; z *= rn;
}

__global__ void k_frames(const float* __restrict__ Ca)
{
    int r = blockIdx.x * blockDim.x + threadIdx.x;
    if (r >= Bc * Lc) return;
    int b = r / Lc, i = r - b * Lc;
    float* O = &g_O[(size_t)r * 9];
    if (i < 1 || i > Lc - 3) {
        #pragma unroll
        for (int t = 0; t < 9; t++) O[t] = 0.f;
        return;
    }
    const float* cab = Ca + (size_t)b * Lc * 3;
    float p0x = cab[(i-1)*3+0], p0y = cab[(i-1)*3+1], p0z = cab[(i-1)*3+2];
    float p1x = cab[(i  )*3+0], p1y = cab[(i  )*3+1], p1z = cab[(i  )*3+2];
    float p2x = cab[(i+1)*3+0], p2y = cab[(i+1)*3+1], p2z = cab[(i+1)*3+2];

    float ax = p1x - p0x, ay = p1y - p0y, az = p1z - p0z;
    float an = sqrtf(ax*ax + ay*ay + az*az + 1e-12f);
    float ab = (an > 3.6f && an < 4.0f) ? 1.f : 0.f;
    float u2x = ax*ab, u2y = ay*ab, u2z = az*ab;
    norml3(u2x, u2y, u2z);

    float bx = p2x - p1x, by = p2y - p1y, bz = p2z - p1z;
    float bn = sqrtf(bx*bx + by*by + bz*bz + 1e-12f);
    float bb = (bn > 3.6f && bn < 4.0f) ? 1.f : 0.f;
    float u1x = bx*bb, u1y = by*bb, u1z = bz*bb;
    norml3(u1x, u1y, u1z);

    float n2x = u2y*u1z - u2z*u1y;
    float n2y = u2z*u1x - u2x*u1z;
    float n2z = u2x*u1y - u2y*u1x;
    norml3(n2x, n2y, n2z);

    float o1x = u2x - u1x, o1y = u2y - u1y, o1z = u2z - u1z;
    norml3(o1x, o1y, o1z);

    float cx = o1y*n2z - o1z*n2y;
    float cy = o1z*n2x - o1x*n2z;
    float cz = o1x*n2y - o1y*n2x;

    O[0] = o1x; O[1] = o1y; O[2] = o1z;
    O[3] = n2x; O[4] = n2y; O[5] = n2z;
    O[6] = cx;  O[7] = cy;  O[8] = cz;
}

// ---------------------------------------------------------------------------
// Kernel 2: top-K (K=30) smallest adjusted distances per (b,i).
// ---------------------------------------------------------------------------
__global__ void k_topk(const float* __restrict__ Ca, const float* __restrict__ mask,
                       float* __restrict__ out, long long out_elems)
{
    int warp = threadIdx.x >> 5;
    int lane = threadIdx.x & 31;
    int r = blockIdx.x * (blockDim.x >> 5) + warp;
    if (r >= Bc * Lc) return;
    int b = r / Lc, i = r - b * Lc;
    const float* cab = Ca + (size_t)b * Lc * 3;
    const float* mb  = mask + (size_t)b * Lc;

    float cix = cab[i*3+0], ciy = cab[i*3+1], ciz = cab[i*3+2];
    float mi  = mb[i];

    float d[NSLOT];
    unsigned long long valid = 0ull;
    float dmax = 0.f;
    #pragma unroll
    for (int s = 0; s < NSLOT; s++) {
        int j = s * 32 + lane;
        float dx = cab[j*3+0] - cix;
        float dy = cab[j*3+1] - ciy;
        float dz = cab[j*3+2] - ciz;
        float dist = sqrtf(dx*dx + dy*dy + dz*dz + 1e-6f);
        float m2 = mi * mb[j];
        float D = m2 * dist;
        d[s] = D;
        if (m2 != 0.f) valid |= (1ull << s);
        dmax = fmaxf(dmax, D);
    }
    #pragma unroll
    for (int o = 16; o; o >>= 1)
        dmax = fmaxf(dmax, __shfl_xor_sync(0xffffffffu, dmax, o));
    #pragma unroll
    for (int s = 0; s < NSLOT; s++)
        if (!((valid >> s) & 1ull)) d[s] = dmax;

    unsigned long long removed = 0ull;
    for (int t = 0; t < Kc; t++) {
        unsigned long long best = ~0ull;
        #pragma unroll
        for (int s = 0; s < NSLOT; s++) {
            if (!((removed >> s) & 1ull)) {
                unsigned long long key =
                    ((unsigned long long)__float_as_uint(d[s]) << 32) |
                    (unsigned)(s * 32 + lane);
                if (key < best) best = key;
            }
        }
        #pragma unroll
        for (int o = 16; o; o >>= 1) {
            unsigned long long oth = __shfl_xor_sync(0xffffffffu, best, o);
            if (oth < best) best = oth;
        }
        int j = (int)(best & 0xffffffffull);
        float val = __uint_as_float((unsigned)(best >> 32));
        if (lane == 0) {
            g_Eidx[(size_t)r * Kc + t] = j;
            g_Dn  [(size_t)r * Kc + t] = val;
            long long off = (long long)Bc * Lc * Kc * EF + (long long)r * Kc + t;
            if (off < out_elems) out[off] = (float)j;   // E_idx as float
        }
        if ((j & 31) == lane) removed |= (1ull << (j >> 5));
    }
}

// ---------------------------------------------------------------------------
// Kernel 3: fused per-(b,i): edge features (151) -> f32x2 GEMM (x128) -> LN
// ---------------------------------------------------------------------------
__device__ __forceinline__ float edist(const float* a, const float* bp)
{
    float dx = a[0]-bp[0], dy = a[1]-bp[1], dz = a[2]-bp[2];
    return sqrtf(dx*dx + dy*dy + dz*dz + 1e-6f);
}
__device__ __forceinline__ float fsign(float x)
{
    return (float)((x > 0.f) - (x < 0.f));
}

__global__ void __launch_bounds__(256)
k_edge(const float* __restrict__ Ca,
       const int* __restrict__ ridx, const int* __restrict__ chain,
       const float* __restrict__ gamma, const float* __restrict__ beta,
       float* __restrict__ out, long long out_elems)
{
    // s_feat: 32 edge rows (30 real + 2 dummy), 152 k-dims; row = 608B (16B aligned)
    __shared__ __align__(16) float s_feat[32][KPAD];
    __shared__ float s_out[32][EF];
    __shared__ float s_dist[Kc][9];
    __shared__ float s_misc[18];        // O_i(9), ci(3), cim(3), cip(3)
    __shared__ int   s_dpos[32];
    __shared__ int   s_ri, s_ch;

    int r = blockIdx.x;
    int b = r / Lc, i = r - b * Lc;
    int tid = threadIdx.x;
    const float* cab = Ca + (size_t)b * Lc * 3;

    // zero feature buffer (covers k-padding and dummy edge rows)
    {
        float4 z4 = make_float4(0.f, 0.f, 0.f, 0.f);
        float4* sf4 = (float4*)s_feat;
        for (int idx = tid; idx < 32 * KPAD / 4; idx += 256) sf4[idx] = z4;
        if (tid < 32) s_dpos[tid] = 0;
    }
    if (tid == 0) {
        #pragma unroll
        for (int t = 0; t < 9; t++) s_misc[t] = g_O[(size_t)r * 9 + t];
        s_misc[ 9] = cab[i*3+0]; s_misc[10] = cab[i*3+1]; s_misc[11] = cab[i*3+2];
        if (i > 0)      { s_misc[12] = cab[(i-1)*3+0]; s_misc[13] = cab[(i-1)*3+1]; s_misc[14] = cab[(i-1)*3+2]; }
        else            { s_misc[12] = 0.f; s_misc[13] = 0.f; s_misc[14] = 0.f; }
        if (i < Lc - 1) { s_misc[15] = cab[(i+1)*3+0]; s_misc[16] = cab[(i+1)*3+1]; s_misc[17] = cab[(i+1)*3+2]; }
        else            { s_misc[15] = 0.f; s_misc[16] = 0.f; s_misc[17] = 0.f; }
        s_ri = ridx[r]; s_ch = chain[r];
    }
    __syncthreads();

    if (tid < Kc) {
        int j = g_Eidx[(size_t)r * Kc + tid];
        const float* Oi  = &s_misc[0];
        const float* ci  = &s_misc[9];
        const float* cim = &s_misc[12];
        const float* cip = &s_misc[15];

        float cj[3], cjm[3], cjp[3];
        cj[0] = cab[j*3+0]; cj[1] = cab[j*3+1]; cj[2] = cab[j*3+2];
        if (j > 0)      { cjm[0] = cab[(j-1)*3+0]; cjm[1] = cab[(j-1)*3+1]; cjm[2] = cab[(j-1)*3+2]; }
        else            { cjm[0] = cjm[1] = cjm[2] = 0.f; }
        if (j < Lc - 1) { cjp[0] = cab[(j+1)*3+0]; cjp[1] = cab[(j+1)*3+1]; cjp[2] = cab[(j+1)*3+2]; }
        else            { cjp[0] = cjp[1] = cjp[2] = 0.f; }

        s_dist[tid][0] = g_Dn[(size_t)r * Kc + tid];
        s_dist[tid][1] = edist(cim, cjm);
        s_dist[tid][2] = edist(cip, cjp);
        s_dist[tid][3] = edist(cim, cj );
        s_dist[tid][4] = edist(cim, cjp);
        s_dist[tid][5] = edist(ci , cjm);
        s_dist[tid][6] = edist(ci , cjp);
        s_dist[tid][7] = edist(cip, cjm);
        s_dist[tid][8] = edist(cip, cj );

        // positional embedding index (projection precomputed in g_T)
        int off = s_ri - ridx[(size_t)b * Lc + j];
        int ech = (s_ch == chain[(size_t)b * Lc + j]);
        s_dpos[tid] = ech ? min(max(off + 32, 0), 64) : 65;

        // dU = norml(O_i @ (Ca_j - Ca_i))  -> dims 144..146
        float vx = cj[0]-ci[0], vy = cj[1]-ci[1], vz = cj[2]-ci[2];
        float w0 = Oi[0]*vx + Oi[1]*vy + Oi[2]*vz;
        float w1 = Oi[3]*vx + Oi[4]*vy + Oi[5]*vz;
        float w2 = Oi[6]*vx + Oi[7]*vy + Oi[8]*vz;
        float rn = rsqrtf(w0*w0 + w1*w1 + w2*w2 + 1e-12f);
        s_feat[tid][144] = w0*rn; s_feat[tid][145] = w1*rn; s_feat[tid][146] = w2*rn;

        // R = O_i^T @ O_j ; quaternion -> dims 147..150
        float Oj[9];
        #pragma unroll
        for (int t = 0; t < 9; t++) Oj[t] = g_O[((size_t)b * Lc + j) * 9 + t];
        float R[3][3];
        #pragma unroll
        for (int a = 0; a < 3; a++)
            #pragma unroll
            for (int m = 0; m < 3; m++)
                R[a][m] = Oi[0*3+a]*Oj[0*3+m] + Oi[1*3+a]*Oj[1*3+m] + Oi[2*3+a]*Oj[2*3+m];
        float Rxx = R[0][0], Ryy = R[1][1], Rzz = R[2][2];
        float mx = 0.5f * sqrtf(fabsf(1.f + Rxx - Ryy - Rzz) + 1e-12f);
        float my = 0.5f * sqrtf(fabsf(1.f - Rxx + Ryy - Rzz) + 1e-12f);
        float mz = 0.5f * sqrtf(fabsf(1.f - Rxx - Ryy + Rzz) + 1e-12f);
        float qx = fsign(R[2][1] - R[1][2]) * mx;
        float qy = fsign(R[0][2] - R[2][0]) * my;
        float qz = fsign(R[1][0] - R[0][1]) * mz;
        float qw = 0.5f * sqrtf(fmaxf(1.f + Rxx + Ryy + Rzz, 0.f) + 1e-12f);
        float qn = rsqrtf(qx*qx + qy*qy + qz*qz + qw*qw + 1e-12f);
        s_feat[tid][147] = qx*qn; s_feat[tid][148] = qy*qn;
        s_feat[tid][149] = qz*qn; s_feat[tid][150] = qw*qn;
    }
    __syncthreads();

    // RBFs: 30 edges x 9 dists x 16 mus -> dims 0..143
    for (int idx = tid; idx < Kc * 144; idx += 256) {
        int e = idx / 144;
        int rem = idx - e * 144;
        int rr = rem >> 4;
        int m = rem & 15;
        float D = s_dist[e][rr];
        float mu = 2.0f + (4.0f / 3.0f) * (float)m;
        float t = (D - mu) * 0.8f;
        s_feat[e][rem] = __expf(-t * t);
    }
    __syncthreads();

    // f32x2 GEMM: 4 edge-groups (8 edges) x 64 threads (2 features each).
    // Accumulator pairs hold {even-k partial, odd-k partial}; combined at end.
    // Seeded from precomputed positional projection g_T (even lane).
    {
        int h  = tid >> 6;          // edge group 0..3 -> edges h*8..h*8+7
        int fq = tid & 63;          // features fq and fq+64
        ull acc[8][2];
        #pragma unroll
        for (int e8 = 0; e8 < 8; e8++) {
            int d = s_dpos[h * 8 + e8];
            acc[e8][0] = (ull)__float_as_uint(g_T[d * EF + fq]);
            acc[e8][1] = (ull)__float_as_uint(g_T[d * EF + fq + 64]);
        }
        #pragma unroll 2
        for (int kg = 0; kg < KG; kg++) {
            ull w00 = g_WK[(2 * kg    ) * EF + fq];
            ull w01 = g_WK[(2 * kg    ) * EF + fq + 64];
            ull w10 = g_WK[(2 * kg + 1) * EF + fq];
            ull w11 = g_WK[(2 * kg + 1) * EF + fq + 64];
            #pragma unroll
            for (int e8 = 0; e8 < 8; e8++) {
                ulonglong2 fe = *(const ulonglong2*)&s_feat[h * 8 + e8][4 * kg];
                FMA_F32X2(acc[e8][0], fe.x, w00);
                FMA_F32X2(acc[e8][1], fe.x, w01);
                FMA_F32X2(acc[e8][0], fe.y, w10);
                FMA_F32X2(acc[e8][1], fe.y, w11);
            }
        }
        #pragma unroll
        for (int e8 = 0; e8 < 8; e8++) {
            int e = h * 8 + e8;
            float lo0 = __uint_as_float((unsigned)(acc[e8][0] & 0xffffffffull));
            float hi0 = __uint_as_float((unsigned)(acc[e8][0] >> 32));
            float lo1 = __uint_as_float((unsigned)(acc[e8][1] & 0xffffffffull));
            float hi1 = __uint_as_float((unsigned)(acc[e8][1] >> 32));
            s_out[e][fq     ] = lo0 + hi0;
            s_out[e][fq + 64] = lo1 + hi1;
        }
    }
    __syncthreads();

    // LayerNorm per edge over 128 features; warp per edge (round-robin)
    {
        int warp = tid >> 5, lane = tid & 31;
        for (int e = warp; e < Kc; e += 8) {
            float v[4];
            #pragma unroll
            for (int q = 0; q < 4; q++) v[q] = s_out[e][lane + 32 * q];
            float sum = v[0] + v[1] + v[2] + v[3];
            #pragma unroll
            for (int o = 16; o; o >>= 1) sum += __shfl_xor_sync(0xffffffffu, sum, o);
            float mu = sum * (1.f / 128.f);
            float ss = 0.f;
            #pragma unroll
            for (int q = 0; q < 4; q++) { float dv = v[q] - mu; ss += dv * dv; }
            #pragma unroll
            for (int o = 16; o; o >>= 1) ss += __shfl_xor_sync(0xffffffffu, ss, o);
            float var = ss * (1.f / 128.f);
            float rstd = rsqrtf(var + 1e-5f);
            long long base = ((long long)r * Kc + e) * EF;
            #pragma unroll
            for (int q = 0; q < 4; q++) {
                int fq = lane + 32 * q;
                long long o2 = base + fq;
                if (o2 < out_elems)
                    out[o2] = (v[q] - mu) * rstd * gamma[fq] + beta[fq];
            }
        }
    }
}

// ---------------------------------------------------------------------------
extern "C" void kernel_launch(void* const* d_in, const int* in_sizes, int n_in,
                              void* d_out, int out_size)
{
    const float* Ca     = (const float*)d_in[0];
    const float* mask   = (const float*)d_in[1];
    const int*   ridx   = (const int*)  d_in[2];
    const int*   chain  = (const int*)  d_in[3];
    const float* W_pos  = (const float*)d_in[4];
    const float* b_pos  = (const float*)d_in[5];
    const float* W_edge = (const float*)d_in[6];
    const float* gamma  = (const float*)d_in[7];
    const float* beta   = (const float*)d_in[8];
    float* out = (float*)d_out;
    long long out_elems = (long long)out_size;

    const int prep_total = (KPAD/2) * EF + 66 * EF;
    k_prep<<<(prep_total + 255) / 256, 256>>>(W_edge, W_pos, b_pos);
    k_frames<<<(Bc * Lc + 255) / 256, 256>>>(Ca);
    k_topk<<<(Bc * Lc) / 8, 256>>>(Ca, mask, out, out_elems);
    k_edge<<<Bc * Lc, 256>>>(Ca, ridx, chain, gamma, beta, out, out_elems);
}